// round 13
// baseline (speedup 1.0000x reference)
#include <cuda_runtime.h>
#include <cuda_bf16.h>
#include <cstdint>

// 3x3 median filter, zero padding, exact median of 9.
// x: (32, 3, 512, 512) fp32 -> 96 images of 512x512.
//
// Persistent blocks + cp.async.bulk double-buffered pipeline:
//   strip = 512 cols x 8 output rows; its 10 input rows are CONTIGUOUS in
//   gmem -> one 20KB bulk-async copy per strip into smem, mbarrier-signaled.
//   While computing strip k from buffer A, the bulk engine fills buffer B
//   with strip k+1 -> global latency fully off the warps' critical path.
// Compute = round-10 exact network (pair-shared sort2 of middle rows,
// pair-shared sliding windows, ~16 FMNMX/px), reading smem (29-cyc LDS),
// zero-pad via clamped indices + exact 0/1 FMUL masks, streaming stores.

#define W 512
#define H 512
#define NIMG 96
#define SR 8                       // output rows per strip
#define INR 10                     // input rows per strip
#define CPBYTES (INR * W * 4)      // 20480
#define NSTRIPS (NIMG * (H / SR))  // 6144
#define GRID 592                   // 4 blocks/SM * 148 SMs

__device__ __forceinline__ uint32_t s2u(const void* p) {
    uint32_t a;
    asm("{ .reg .u64 t; cvta.to.shared.u64 t, %1; cvt.u32.u64 %0, t; }"
        : "=r"(a) : "l"(p));
    return a;
}
__device__ __forceinline__ void mbar_init(uint32_t a, uint32_t n) {
    asm volatile("mbarrier.init.shared.b64 [%0], %1;" :: "r"(a), "r"(n) : "memory");
}
__device__ __forceinline__ void mbar_expect(uint32_t a, uint32_t bytes) {
    asm volatile("mbarrier.arrive.expect_tx.shared.b64 _, [%0], %1;"
                 :: "r"(a), "r"(bytes) : "memory");
}
__device__ __forceinline__ void bulk_ld(uint32_t dst, const float* src, uint32_t mbar) {
    asm volatile(
        "cp.async.bulk.shared::cta.global.mbarrier::complete_tx::bytes [%0], [%1], %2, [%3];"
        :: "r"(dst), "l"(src), "r"((uint32_t)CPBYTES), "r"(mbar) : "memory");
}
__device__ __forceinline__ void mbar_wait(uint32_t a, uint32_t parity) {
    asm volatile(
        "{\n\t"
        ".reg .pred P;\n\t"
        "WL_%=:\n\t"
        "mbarrier.try_wait.parity.acquire.cta.shared::cta.b64 P, [%0], %1, 0x989680;\n\t"
        "@!P bra WL_%=;\n\t"
        "}"
        :: "r"(a), "r"(parity) : "memory");
}

__device__ __forceinline__ float med3(float a, float b, float c) {
    return fmaxf(fminf(a, b), fminf(fmaxf(a, b), c));
}

// Emit one output row: insert row a into (mn, mx) = sort2 of the other two
// rows, combine 3-wide windows with pair sharing, streaming-store a float4.
__device__ __forceinline__ void emit_row(const float* a, const float* mn,
                                         const float* mx,
                                         float* __restrict__ outp) {
    float lo[6], mi[6], hi[6];
    #pragma unroll
    for (int i = 0; i < 6; i++) {
        lo[i] = fminf(a[i], mn[i]);
        hi[i] = fmaxf(a[i], mx[i]);
        mi[i] = fmaxf(mn[i], fminf(a[i], mx[i]));
    }
    float o[4];
    #pragma unroll
    for (int t = 0; t < 2; t++) {
        const int i = 2 * t + 1;
        const float A = fmaxf(lo[i], lo[i + 1]);
        const float B = fminf(hi[i], hi[i + 1]);
        const float n = fminf(mi[i], mi[i + 1]);
        const float m = fmaxf(mi[i], mi[i + 1]);
        o[2 * t]     = med3(fmaxf(A, lo[2 * t]),
                            fmaxf(n, fminf(m, mi[2 * t])),
                            fminf(B, hi[2 * t]));
        o[2 * t + 1] = med3(fmaxf(A, lo[2 * t + 3]),
                            fminf(m, fmaxf(n, mi[2 * t + 3])),
                            fminf(B, hi[2 * t + 3]));
    }
    float4 res; res.x = o[0]; res.y = o[1]; res.z = o[2]; res.w = o[3];
    __stcs(reinterpret_cast<float4*>(outp), res);
}

__global__ void __launch_bounds__(256, 4)
median3x3_kernel(const float* __restrict__ x, float* __restrict__ out) {
    __shared__ __align__(16) float sb[2][INR * W];
    __shared__ __align__(8) unsigned long long mbar_s[2];

    const int tid = threadIdx.x;
    const uint32_t mb[2] = { s2u(&mbar_s[0]), s2u(&mbar_s[1]) };
    const uint32_t sbu[2] = { s2u(&sb[0][0]), s2u(&sb[1][0]) };

    if (tid == 0) {
        mbar_init(mb[0], 1);
        mbar_init(mb[1], 1);
        asm volatile("fence.proxy.async.shared::cta;" ::: "memory");
    }
    __syncthreads();

    const int col = tid & 127;          // column thread 0..127
    const int h   = tid >> 7;           // row half 0/1
    const int cb  = col << 2;           // column base 0..508
    const int cl  = (cb == 0)     ? 0     : cb - 1;
    const int cr  = (cb == W - 4) ? W - 1 : cb + 4;
    const float ml = (cb > 0)     ? 1.0f : 0.0f;
    const float mr = (cb < W - 4) ? 1.0f : 0.0f;

    int s = blockIdx.x;
    // Prologue: issue first strip's bulk load into buffer 0.
    if (tid == 0 && s < NSTRIPS) {
        const int img0 = s >> 6;
        const int y00  = (s & 63) << 3;
        const int st0  = min(max(y00 - 1, 0), H - INR);
        mbar_expect(mb[0], CPBYTES);
        bulk_ld(sbu[0], x + img0 * (H * W) + st0 * W, mb[0]);
    }

    int it = 0;
    for (; s < NSTRIPS; s += GRID, it++) {
        const int buf = it & 1;
        const int nxt = s + GRID;

        // Ensure previous compute on the other buffer finished, then prefetch.
        if (it > 0) __syncthreads();
        if (tid == 0 && nxt < NSTRIPS) {
            const int imgn = nxt >> 6;
            const int y0n  = (nxt & 63) << 3;
            const int stn  = min(max(y0n - 1, 0), H - INR);
            mbar_expect(mb[buf ^ 1], CPBYTES);
            bulk_ld(sbu[buf ^ 1], x + imgn * (H * W) + stn * W, mb[buf ^ 1]);
        }

        // Wait for this strip's data.
        mbar_wait(mb[buf], (it >> 1) & 1);

        const int img   = s >> 6;
        const int y0    = (s & 63) << 3;
        const int start = min(max(y0 - 1, 0), H - INR);
        const float* S  = sb[buf];

        // This half's 6 input rows: global rows r0g .. r0g+5.
        const int r0g = y0 + 4 * h - 1;
        const float mt  = (r0g >= 0)        ? 1.0f : 0.0f;   // row k=0 valid
        const float mbm = (r0g + 5 <= H - 1) ? 1.0f : 0.0f;  // row k=5 valid
        const int i0 = max(r0g, 0) - start;
        const int i5 = min(r0g + 5, H - 1) - start;
        const int ib = r0g + 1 - start;     // rows k=1..4 at ib .. ib+3

        float ra[6], rb[6], rc[6], rd[6], re[6], rf[6];
        float mn[6], mx[6];

        // Load 6 rows from smem (batched LDS; masks on fma pipe).
        {
            const float* rp = S + i0 * W;
            const float4 v = *reinterpret_cast<const float4*>(rp + cb);
            ra[0] = rp[cl] * (ml * mt);
            ra[1] = v.x * mt; ra[2] = v.y * mt; ra[3] = v.z * mt; ra[4] = v.w * mt;
            ra[5] = rp[cr] * (mr * mt);
        }
        {
            const float* rp = S + ib * W;
            const float4 v = *reinterpret_cast<const float4*>(rp + cb);
            rb[0] = rp[cl] * ml;
            rb[1] = v.x; rb[2] = v.y; rb[3] = v.z; rb[4] = v.w;
            rb[5] = rp[cr] * mr;
        }
        {
            const float* rp = S + (ib + 1) * W;
            const float4 v = *reinterpret_cast<const float4*>(rp + cb);
            rc[0] = rp[cl] * ml;
            rc[1] = v.x; rc[2] = v.y; rc[3] = v.z; rc[4] = v.w;
            rc[5] = rp[cr] * mr;
        }
        {
            const float* rp = S + (ib + 2) * W;
            const float4 v = *reinterpret_cast<const float4*>(rp + cb);
            rd[0] = rp[cl] * ml;
            rd[1] = v.x; rd[2] = v.y; rd[3] = v.z; rd[4] = v.w;
            rd[5] = rp[cr] * mr;
        }
        {
            const float* rp = S + (ib + 3) * W;
            const float4 v = *reinterpret_cast<const float4*>(rp + cb);
            re[0] = rp[cl] * ml;
            re[1] = v.x; re[2] = v.y; re[3] = v.z; re[4] = v.w;
            re[5] = rp[cr] * mr;
        }
        {
            const float* rp = S + i5 * W;
            const float4 v = *reinterpret_cast<const float4*>(rp + cb);
            rf[0] = rp[cl] * (ml * mbm);
            rf[1] = v.x * mbm; rf[2] = v.y * mbm; rf[3] = v.z * mbm; rf[4] = v.w * mbm;
            rf[5] = rp[cr] * (mr * mbm);
        }

        float* op = out + img * (H * W) + (y0 + 4 * h) * W + cb;

        // pair 0: outputs rows (y0+4h), (y0+4h+1)
        #pragma unroll
        for (int i = 0; i < 6; i++) {
            mn[i] = fminf(rb[i], rc[i]);
            mx[i] = fmaxf(rb[i], rc[i]);
        }
        emit_row(ra, mn, mx, op);
        emit_row(rd, mn, mx, op + W);

        // pair 1: outputs rows (y0+4h+2), (y0+4h+3)
        #pragma unroll
        for (int i = 0; i < 6; i++) {
            mn[i] = fminf(rd[i], re[i]);
            mx[i] = fmaxf(rd[i], re[i]);
        }
        emit_row(rc, mn, mx, op + 2 * W);
        emit_row(rf, mn, mx, op + 3 * W);
    }
}

extern "C" void kernel_launch(void* const* d_in, const int* in_sizes, int n_in,
                              void* d_out, int out_size) {
    const float* x = (const float*)d_in[0];
    float* out = (float*)d_out;
    median3x3_kernel<<<GRID, 256>>>(x, out);
}

// round 14
// speedup vs baseline: 1.0511x; 1.0511x over previous
#include <cuda_runtime.h>
#include <cuda_bf16.h>
#include <cstdint>

// 3x3 median filter, zero padding, exact median of 9.
// x: (32, 3, 512, 512) fp32 -> 96 images of 512x512.
//
// Persistent blocks + cp.async.bulk double-buffered pipeline.
// Strip = 512 cols x 8 output rows; its 10 input rows are contiguous ->
// one 20KB bulk-async copy per strip, mbarrier-signaled, overlapping the
// previous strip's compute. Compute reads smem (29-cyc LDS) in the
// round-10 consumption order (low register pressure), exact min/max
// network, one row-mask per thread-half, streaming stores.
// __launch_bounds__(256,5): 51-reg cap -> 5 blocks/SM (smem: 5x41KB OK).

#define W 512
#define H 512
#define NIMG 96
#define INR 10                     // input rows per strip
#define CPBYTES (INR * W * 4)      // 20480
#define NSTRIPS (NIMG * (H / 8))   // 6144
#define GRID 740                   // 5 blocks/SM * 148 SMs

__device__ __forceinline__ uint32_t s2u(const void* p) {
    uint32_t a;
    asm("{ .reg .u64 t; cvta.to.shared.u64 t, %1; cvt.u32.u64 %0, t; }"
        : "=r"(a) : "l"(p));
    return a;
}
__device__ __forceinline__ void mbar_init(uint32_t a, uint32_t n) {
    asm volatile("mbarrier.init.shared.b64 [%0], %1;" :: "r"(a), "r"(n) : "memory");
}
__device__ __forceinline__ void mbar_expect(uint32_t a, uint32_t bytes) {
    asm volatile("mbarrier.arrive.expect_tx.shared.b64 _, [%0], %1;"
                 :: "r"(a), "r"(bytes) : "memory");
}
__device__ __forceinline__ void bulk_ld(uint32_t dst, const float* src, uint32_t mbar) {
    asm volatile(
        "cp.async.bulk.shared::cta.global.mbarrier::complete_tx::bytes [%0], [%1], %2, [%3];"
        :: "r"(dst), "l"(src), "r"((uint32_t)CPBYTES), "r"(mbar) : "memory");
}
__device__ __forceinline__ void mbar_wait(uint32_t a, uint32_t parity) {
    asm volatile(
        "{\n\t"
        ".reg .pred P;\n\t"
        "WL_%=:\n\t"
        "mbarrier.try_wait.parity.acquire.cta.shared::cta.b64 P, [%0], %1, 0x989680;\n\t"
        "@!P bra WL_%=;\n\t"
        "}"
        :: "r"(a), "r"(parity) : "memory");
}

__device__ __forceinline__ float med3(float a, float b, float c) {
    return fmaxf(fminf(a, b), fminf(fmaxf(a, b), c));
}

// Load one smem row's 6-col window; optional mask (exact 0/1 FMUL).
__device__ __forceinline__ void srow(const float* __restrict__ rp,
                                     int cb, int cl, int cr,
                                     float ml, float mr, float mrow,
                                     float* c) {
    const float4 v = *reinterpret_cast<const float4*>(rp + cb);
    c[0] = rp[cl] * (ml * mrow);
    c[1] = v.x * mrow; c[2] = v.y * mrow;
    c[3] = v.z * mrow; c[4] = v.w * mrow;
    c[5] = rp[cr] * (mr * mrow);
}
__device__ __forceinline__ void srow_n(const float* __restrict__ rp,
                                       int cb, int cl, int cr,
                                       float ml, float mr, float* c) {
    const float4 v = *reinterpret_cast<const float4*>(rp + cb);
    c[0] = rp[cl] * ml;
    c[1] = v.x; c[2] = v.y; c[3] = v.z; c[4] = v.w;
    c[5] = rp[cr] * mr;
}

// Emit one output row: insert row a into (mn, mx) = sort2 of the other two
// rows, combine 3-wide windows with pair sharing, streaming-store a float4.
__device__ __forceinline__ void emit_row(const float* a, const float* mn,
                                         const float* mx,
                                         float* __restrict__ outp) {
    float lo[6], mi[6], hi[6];
    #pragma unroll
    for (int i = 0; i < 6; i++) {
        lo[i] = fminf(a[i], mn[i]);
        hi[i] = fmaxf(a[i], mx[i]);
        mi[i] = fmaxf(mn[i], fminf(a[i], mx[i]));
    }
    float o[4];
    #pragma unroll
    for (int t = 0; t < 2; t++) {
        const int i = 2 * t + 1;
        const float A = fmaxf(lo[i], lo[i + 1]);
        const float B = fminf(hi[i], hi[i + 1]);
        const float n = fminf(mi[i], mi[i + 1]);
        const float m = fmaxf(mi[i], mi[i + 1]);
        o[2 * t]     = med3(fmaxf(A, lo[2 * t]),
                            fmaxf(n, fminf(m, mi[2 * t])),
                            fminf(B, hi[2 * t]));
        o[2 * t + 1] = med3(fmaxf(A, lo[2 * t + 3]),
                            fminf(m, fmaxf(n, mi[2 * t + 3])),
                            fminf(B, hi[2 * t + 3]));
    }
    float4 res; res.x = o[0]; res.y = o[1]; res.z = o[2]; res.w = o[3];
    __stcs(reinterpret_cast<float4*>(outp), res);
}

__global__ void __launch_bounds__(256, 5)
median3x3_kernel(const float* __restrict__ x, float* __restrict__ out) {
    __shared__ __align__(16) float sb[2][INR * W];
    __shared__ __align__(8) unsigned long long mbar_s[2];

    const int tid = threadIdx.x;
    const uint32_t mb0 = s2u(&mbar_s[0]), mb1 = s2u(&mbar_s[1]);
    const uint32_t sb0 = s2u(&sb[0][0]), sb1 = s2u(&sb[1][0]);

    if (tid == 0) {
        mbar_init(mb0, 1);
        mbar_init(mb1, 1);
        asm volatile("fence.proxy.async.shared::cta;" ::: "memory");
    }
    __syncthreads();

    const int cb = (tid & 127) << 2;    // column base 0..508
    const int h  = tid >> 7;            // row half 0/1
    const int cl = (cb == 0)     ? 0     : cb - 1;
    const int cr = (cb == W - 4) ? W - 1 : cb + 4;
    const float ml = (cb > 0)     ? 1.0f : 0.0f;
    const float mr = (cb < W - 4) ? 1.0f : 0.0f;

    int s = blockIdx.x;
    if (tid == 0) {
        const int y00 = (s & 63) << 3;
        const int st0 = min(max(y00 - 1, 0), H - INR);
        mbar_expect(mb0, CPBYTES);
        bulk_ld(sb0, x + (s >> 6) * (H * W) + st0 * W, mb0);
    }

    int it = 0;
    for (; s < NSTRIPS; s += GRID, it++) {
        const int buf = it & 1;
        const int nxt = s + GRID;

        if (it > 0) __syncthreads();          // buffer free before overwrite
        if (tid == 0 && nxt < NSTRIPS) {
            const int y0n = (nxt & 63) << 3;
            const int stn = min(max(y0n - 1, 0), H - INR);
            mbar_expect(buf ? mb0 : mb1, CPBYTES);
            bulk_ld(buf ? sb0 : sb1, x + (nxt >> 6) * (H * W) + stn * W,
                    buf ? mb0 : mb1);
        }

        mbar_wait(buf ? mb1 : mb0, (it >> 1) & 1);

        const int y0    = (s & 63) << 3;
        const int start = min(max(y0 - 1, 0), H - INR);
        const float* S  = buf ? sb[1] : sb[0];

        // This half covers output rows yb..yb+3, inputs yb-1..yb+4.
        const int yb  = y0 + (h << 2);
        const int r0g = yb - 1;
        // h=0: bottom row (yb+4 <= 508) always valid; h=1: top row always valid.
        const float mtop = (h == 0) ? ((y0 > 0) ? 1.0f : 0.0f) : 1.0f;
        const float mbot = (h == 1) ? ((y0 < H - 8) ? 1.0f : 0.0f) : 1.0f;
        const int i0 = max(r0g, 0) - start;          // smem idx of row yb-1
        const int i5 = min(r0g + 5, H - 1) - start;  // smem idx of row yb+4
        const int ib = r0g + 1 - start;              // rows yb..yb+3

        float ra[6], rb[6], rc[6], rd[6], re[6], rf[6];
        float mn[6], mx[6];

        float* op = out + (s >> 6) * (H * W) + yb * W + cb;

        // --- pair 0 (R10 order) ---
        srow  (S + i0 * W,       cb, cl, cr, ml, mr, mtop, ra);
        srow_n(S + ib * W,       cb, cl, cr, ml, mr, rb);
        srow_n(S + (ib + 1) * W, cb, cl, cr, ml, mr, rc);
        srow_n(S + (ib + 2) * W, cb, cl, cr, ml, mr, rd);

        #pragma unroll
        for (int i = 0; i < 6; i++) {          // rb dead after this
            mn[i] = fminf(rb[i], rc[i]);
            mx[i] = fmaxf(rb[i], rc[i]);
        }
        emit_row(ra, mn, mx, op);              // ra dead
        emit_row(rd, mn, mx, op + W);          // mn,mx dead

        // --- pair 1 ---
        srow_n(S + (ib + 3) * W, cb, cl, cr, ml, mr, re);
        srow  (S + i5 * W,       cb, cl, cr, ml, mr, mbot, rf);

        #pragma unroll
        for (int i = 0; i < 6; i++) {
            mn[i] = fminf(rd[i], re[i]);
            mx[i] = fmaxf(rd[i], re[i]);
        }
        emit_row(rc, mn, mx, op + 2 * W);
        emit_row(rf, mn, mx, op + 3 * W);
    }
}

extern "C" void kernel_launch(void* const* d_in, const int* in_sizes, int n_in,
                              void* d_out, int out_size) {
    const float* x = (const float*)d_in[0];
    float* out = (float*)d_out;
    median3x3_kernel<<<GRID, 256>>>(x, out);
}